// round 3
// baseline (speedup 1.0000x reference)
#include <cuda_runtime.h>

// v: [8][1024][8][64] f32, w: [1][8][63] f32, out: [8][1024][8][64] f32
// Factorization (s=32, j = a*32+b, l = c*32+e):
//   out[n,j,hd] = A[n,a,hd] + B[n,b,hd]
//   A = bias @ R,  B = bias @ C,  R[c]=sum_e v[c*32+e], C[e]=sum_c v[c*32+e]
//   bias[h,j,k] = w[h, (32 - k + j) mod 63]

#define NB   8
#define S    32
#define HD   512
#define HD4  128

__device__ float4 g_R[NB * S * HD4];
__device__ float4 g_C[NB * S * HD4];
__device__ float4 g_A[NB * S * HD4];
__device__ float4 g_B[NB * S * HD4];

// ---------------------------------------------------------------------------
// Kernel 1: R and C partial sums. grid=512 (256 R + 256 C), block=512.
// ---------------------------------------------------------------------------
__global__ void rc_kernel(const float4* __restrict__ v4) {
    int bid = blockIdx.x;
    bool isC = bid >= 256;
    int nb = bid & 255;
    int n = nb >> 5;
    int k = nb & 31;
    int t = threadIdx.x;
    int col = t & 127;
    int rg = t >> 7;

    const float4* base = v4 + (size_t)n * 1024 * HD4;
    float4 acc = make_float4(0.f, 0.f, 0.f, 0.f);

    if (!isC) {
        const float4* p = base + (size_t)(k * 32 + rg * 8) * HD4 + col;
        #pragma unroll
        for (int i = 0; i < 8; ++i) {
            float4 x = p[i * HD4];
            acc.x += x.x; acc.y += x.y; acc.z += x.z; acc.w += x.w;
        }
    } else {
        const float4* p = base + (size_t)(rg * 8 * 32 + k) * HD4 + col;
        #pragma unroll
        for (int i = 0; i < 8; ++i) {
            float4 x = p[i * 32 * HD4];
            acc.x += x.x; acc.y += x.y; acc.z += x.z; acc.w += x.w;
        }
    }

    __shared__ float4 s[512];
    s[t] = acc;
    __syncthreads();

    if (rg == 0) {
        float4 a = s[col], b = s[col + 128], c = s[col + 256], d = s[col + 384];
        float4 r;
        r.x = (a.x + b.x) + (c.x + d.x);
        r.y = (a.y + b.y) + (c.y + d.y);
        r.z = (a.z + b.z) + (c.z + d.z);
        r.w = (a.w + b.w) + (c.w + d.w);
        (isC ? g_C : g_R)[(n * S + k) * HD4 + col] = r;
    }
}

// ---------------------------------------------------------------------------
// Kernel 2: A = bias @ R (which=0), B = bias @ C (which=1).
// grid = 128 (which x n x h), block = 256. One barrier, 8 outputs/thread.
// ---------------------------------------------------------------------------
__global__ void ab_kernel(const float* __restrict__ w) {
    int blk   = blockIdx.x;
    int h     = blk & 7;
    int n     = (blk >> 3) & 7;
    int which = blk >> 6;
    int tid   = threadIdx.x;

    __shared__ float sb[32][33];
    __shared__ float ssrc[32][64];

    for (int idx = tid; idx < 1024; idx += 256) {
        int j = idx >> 5, k = idx & 31;
        sb[j][k] = w[h * 63 + ((32 - k + j) % 63)];
    }
    const float4* src4 = which ? g_C : g_R;
    for (int idx = tid; idx < 512; idx += 256) {
        int k = idx >> 4, d4 = idx & 15;
        reinterpret_cast<float4*>(&ssrc[k][0])[d4] = src4[(n * S + k) * HD4 + h * 16 + d4];
    }
    __syncthreads();

    float* dst = (float*)(which ? g_B : g_A);
    int d  = tid & 63;
    int a0 = tid >> 6;            // 0..3
    #pragma unroll
    for (int ai = 0; ai < 8; ++ai) {
        int a = a0 * 8 + ai;
        float acc = 0.f;
        #pragma unroll
        for (int k = 0; k < 32; ++k)
            acc = fmaf(sb[a][k], ssrc[k][d], acc);
        dst[(n * S + a) * HD + h * 64 + d] = acc;
    }
}

// ---------------------------------------------------------------------------
// Kernel 3: out[n, a*32+b, h, d] = A[n,a,hd] + B[n,b,hd]. Pure streaming.
// grid = 4096 x 256, one float4 per thread, fully coalesced store.
// ---------------------------------------------------------------------------
__global__ void out_kernel(float4* __restrict__ out4) {
    int g = blockIdx.x * 256 + threadIdx.x;   // 0 .. 2^20-1
    int d4 = g & 15;
    int h  = (g >> 4) & 7;
    int j  = (g >> 7) & 1023;
    int n  = g >> 17;
    int a  = j >> 5;
    int b  = j & 31;
    int col4 = h * 16 + d4;

    float4 x = g_A[(n * S + a) * HD4 + col4];
    float4 y = g_B[(n * S + b) * HD4 + col4];
    x.x += y.x; x.y += y.y; x.z += y.z; x.w += y.w;
    out4[g] = x;
}

extern "C" void kernel_launch(void* const* d_in, const int* in_sizes, int n_in,
                              void* d_out, int out_size) {
    const float* v = (const float*)d_in[0];
    const float* w = (const float*)d_in[1];
    if (n_in >= 2 && in_sizes[0] < in_sizes[1]) {
        const float* tmp = v; v = w; w = tmp;
    }

    rc_kernel<<<512, 512>>>((const float4*)v);
    ab_kernel<<<128, 256>>>(w);
    out_kernel<<<4096, 256>>>((float4*)d_out);
}

// round 4
// speedup vs baseline: 1.9552x; 1.9552x over previous
#include <cuda_runtime.h>

// v: [8][1024][8][64] f32, w: [1][8][63] f32, out: [8][1024][8][64] f32
// Factorization (s=32, j = a*32+b, l = c*32+e):
//   out[n,j,h,d] = A[n,h,a,d] + B[n,h,b,d]
//   A = bias @ R,  B = bias @ C
//   R[c,d] = sum_e v[n, c*32+e, h, d],  C[e,d] = sum_c v[n, c*32+e, h, d]
//   bias[h,j,k] = w[h, (32 - k + j) mod 63]
//
// SINGLE fused kernel: block = (n, h, d-half). 128 blocks x 512 threads.
// Each block reads its 128KB v slice (pass1 from DRAM/L2, pass2 L1-hit),
// builds R,C,A,B in smem, writes its 128KB out slice. One launch, one wave.

__global__ __launch_bounds__(512, 1)
void fused_kernel(const float4* __restrict__ v4,
                  const float*  __restrict__ w,
                  float4* __restrict__ out4) {
    int blk = blockIdx.x;
    int p = blk & 1;               // d-half: floats [p*32, p*32+32) = 8 float4
    int h = (blk >> 1) & 7;
    int n = blk >> 4;
    int tid = threadIdx.x;

    __shared__ float4 sRp[2][32][8];   // pass-1 partials (eh split)
    __shared__ float4 sCp[2][32][8];   // pass-2 partials (ch split)
    __shared__ float4 sR[32][8], sC[32][8];
    __shared__ float4 sA[32][8], sB[32][8];
    __shared__ float  sb[32][33];      // bias[j][k], padded

    // Thread decomposition for the reduction passes:
    //   c (or e) = tid>>4, eh/ch = (tid>>3)&1, d4 = tid&7
    int c  = tid >> 4;
    int eh = (tid >> 3) & 1;
    int d4 = tid & 7;

    const float4* base = v4 + ((size_t)n * 1024) * 128 + h * 16 + p * 8 + d4;

    // ---- Pass 1: R[c][d] partials. rows l = c*32 + eh*16 + i (contiguous) ----
    {
        const float4* pv = base + (size_t)(c * 32 + eh * 16) * 128;
        float4 acc = make_float4(0.f, 0.f, 0.f, 0.f);
        #pragma unroll
        for (int i = 0; i < 16; ++i) {
            float4 x = pv[i * 128];
            acc.x += x.x; acc.y += x.y; acc.z += x.z; acc.w += x.w;
        }
        sRp[eh][c][d4] = acc;
    }

    // ---- Pass 2: C[e][d] partials. rows l = (ch*16+i)*32 + e (L1 re-hit) ----
    {
        const float4* pv = base + (size_t)(eh * 16 * 32 + c) * 128;
        float4 acc = make_float4(0.f, 0.f, 0.f, 0.f);
        #pragma unroll
        for (int i = 0; i < 16; ++i) {
            float4 x = pv[i * 32 * 128];
            acc.x += x.x; acc.y += x.y; acc.z += x.z; acc.w += x.w;
        }
        sCp[eh][c][d4] = acc;
    }

    // ---- bias tile ----
    for (int idx = tid; idx < 1024; idx += 512) {
        int j = idx >> 5, k = idx & 31;
        sb[j][k] = w[h * 63 + ((32 - k + j) % 63)];
    }
    __syncthreads();

    // ---- combine partials ----
    if (tid < 512) {
        int t = tid & 255;
        int kk = t >> 3, dd = t & 7;
        if (tid < 256) {
            float4 a = sRp[0][kk][dd], b = sRp[1][kk][dd];
            a.x += b.x; a.y += b.y; a.z += b.z; a.w += b.w;
            sR[kk][dd] = a;
        } else {
            float4 a = sCp[0][kk][dd], b = sCp[1][kk][dd];
            a.x += b.x; a.y += b.y; a.z += b.z; a.w += b.w;
            sC[kk][dd] = a;
        }
    }
    __syncthreads();

    // ---- A = bias @ R (tid<256... which=0), B = bias @ C (which=1) ----
    {
        int which = tid >> 8;              // 0 or 1
        int a = (tid >> 3) & 31;
        float4 acc = make_float4(0.f, 0.f, 0.f, 0.f);
        const float4 (*src)[8] = which ? sC : sR;
        #pragma unroll
        for (int k = 0; k < 32; ++k) {
            float f = sb[a][k];
            float4 x = src[k][d4];
            acc.x = fmaf(f, x.x, acc.x);
            acc.y = fmaf(f, x.y, acc.y);
            acc.z = fmaf(f, x.z, acc.z);
            acc.w = fmaf(f, x.w, acc.w);
        }
        (which ? sB : sA)[a][d4] = acc;
    }
    __syncthreads();

    // ---- write out: j = i*64 + jg, out[n,j,h,p*32+..] = A[a] + B[b] ----
    {
        int jg = tid >> 3;                 // 0..63
        float4* po = out4 + ((size_t)n * 1024) * 128 + h * 16 + p * 8 + d4;
        #pragma unroll
        for (int i = 0; i < 16; ++i) {
            int j = i * 64 + jg;
            int a = j >> 5, b = j & 31;
            float4 x = sA[a][d4];
            float4 y = sB[b][d4];
            x.x += y.x; x.y += y.y; x.z += y.z; x.w += y.w;
            po[(size_t)j * 128] = x;
        }
    }
}

extern "C" void kernel_launch(void* const* d_in, const int* in_sizes, int n_in,
                              void* d_out, int out_size) {
    const float* v = (const float*)d_in[0];
    const float* w = (const float*)d_in[1];
    if (n_in >= 2 && in_sizes[0] < in_sizes[1]) {
        const float* tmp = v; v = w; w = tmp;
    }

    fused_kernel<<<128, 512>>>((const float4*)v, w, (float4*)d_out);
}